// round 1
// baseline (speedup 1.0000x reference)
#include <cuda_runtime.h>
#include <cuda_bf16.h>

// ContourIntegrationLayer: depthwise 3x3 conv (center tap zeroed) + residual.
// x: [B=32, H=56, W=56, C=256] fp32 NHWC ; kernel: [3,3,256] fp32.
// Strategy: register sliding window over H. Thread = (b, w, c4) owning a
// float4 channel slice; walks H_SEG rows keeping the 3x3 float4 tap window
// in registers. 3 new float4 loads per output, residual free (window center).

#define BD 32
#define HD 56
#define WD 56
#define CD 256
#define C4D 64            // CD / 4 float4 lanes
#define H_SEG 14          // 56 / 4 segments
#define W_TILE 4

__device__ __forceinline__ void fma4(float4& a, const float4& k, const float4& v) {
    a.x = fmaf(k.x, v.x, a.x);
    a.y = fmaf(k.y, v.y, a.y);
    a.z = fmaf(k.z, v.z, a.z);
    a.w = fmaf(k.w, v.w, a.w);
}

__global__ __launch_bounds__(256)
void contour_integration_kernel(const float* __restrict__ x,
                                const float* __restrict__ ker,
                                float* __restrict__ out) {
    const int c4   = threadIdx.x;                       // 0..63
    const int w    = blockIdx.x * W_TILE + threadIdx.y; // 0..55
    const int h0   = blockIdx.y * H_SEG;                // segment start row
    const int b    = blockIdx.z;

    // Per-channel 3x3 kernel taps (center (1,1) excluded by construction).
    const float4* kp = (const float4*)ker;
    const float4 k00 = kp[0 * C4D + c4];
    const float4 k01 = kp[1 * C4D + c4];
    const float4 k02 = kp[2 * C4D + c4];
    const float4 k10 = kp[3 * C4D + c4];
    const float4 k12 = kp[5 * C4D + c4];
    const float4 k20 = kp[6 * C4D + c4];
    const float4 k21 = kp[7 * C4D + c4];
    const float4 k22 = kp[8 * C4D + c4];

    const bool wl = (w > 0);
    const bool wr = (w < WD - 1);
    const float4 z = make_float4(0.f, 0.f, 0.f, 0.f);

    const float4* xp = (const float4*)x;
    float4*       op = (float4*)out;

    const long rowstride = (long)WD * C4D;                       // float4 units per row
    const long base = ((long)b * HD * WD + (long)w) * C4D + c4;  // pixel (b,0,w) slice

    // Sliding window registers: r<row><tap>, rows h-1,h,h+1 ; taps w-1,w,w+1.
    float4 r00, r01, r02, r10, r11, r12, r20, r21, r22;

    // Preload row h0-1 (zeros above image top) and row h0.
    {
        const int h = h0 - 1;
        if (h >= 0) {
            const float4* p = xp + base + (long)h * rowstride;
            r01 = p[0];
            r00 = wl ? p[-C4D] : z;
            r02 = wr ? p[ C4D] : z;
        } else {
            r00 = z; r01 = z; r02 = z;
        }
    }
    {
        const float4* p = xp + base + (long)h0 * rowstride;
        r11 = p[0];
        r10 = wl ? p[-C4D] : z;
        r12 = wr ? p[ C4D] : z;
    }

    #pragma unroll
    for (int i = 0; i < H_SEG; ++i) {
        const int h  = h0 + i;
        const int hn = h + 1;

        // Load next row (zeros below image bottom).
        if (hn < HD) {
            const float4* p = xp + base + (long)hn * rowstride;
            r21 = p[0];
            r20 = wl ? p[-C4D] : z;
            r22 = wr ? p[ C4D] : z;
        } else {
            r20 = z; r21 = z; r22 = z;
        }

        // acc = residual (x at center) + 8 masked taps.
        float4 a = r11;
        fma4(a, k00, r00);
        fma4(a, k01, r01);
        fma4(a, k02, r02);
        fma4(a, k10, r10);
        fma4(a, k12, r12);
        fma4(a, k20, r20);
        fma4(a, k21, r21);
        fma4(a, k22, r22);

        op[base + (long)h * rowstride] = a;

        // Rotate window down one row.
        r00 = r10; r01 = r11; r02 = r12;
        r10 = r20; r11 = r21; r12 = r22;
    }
}

extern "C" void kernel_launch(void* const* d_in, const int* in_sizes, int n_in,
                              void* d_out, int out_size) {
    const float* x   = (const float*)d_in[0];   // [32,56,56,256]
    const float* ker = (const float*)d_in[1];   // [3,3,256]
    float*       out = (float*)d_out;

    dim3 block(C4D, W_TILE);                       // 64 x 4 = 256 threads
    dim3 grid(WD / W_TILE, HD / H_SEG, BD);        // 14 x 4 x 32 = 1792 blocks
    contour_integration_kernel<<<grid, block>>>(x, ker, out);
}

// round 3
// speedup vs baseline: 1.0929x; 1.0929x over previous
#include <cuda_runtime.h>
#include <cuda_bf16.h>

// ContourIntegrationLayer: depthwise 3x3 conv (center tap zeroed) + residual.
// x: [B=32, H=56, W=56, C=256] fp32 NHWC ; kernel: [3,3,256] fp32.
//
// R2 (resubmit; prior bench was an infra failure): rotating-accumulator
// formulation. Each input row is loaded ONCE (3 unconditional float4 LDGs,
// clamped addresses, boundary handled by zeroing taps) and immediately
// contributes to the partial sums of the three output rows it touches.
// Live state: 2 accumulators + 8 taps -> fits 64 regs -> 4 blocks/SM.
// Loads are independent of the accumulator chain so ptxas can batch them
// across the unrolled loop (higher MLP).

#define BD 32
#define HD 56
#define WD 56
#define CD 256
#define C4D 64            // CD / 4 float4 lanes
#define H_SEG 14          // 56 / 4 segments
#define W_TILE 4

__device__ __forceinline__ float4 f4z() { return make_float4(0.f, 0.f, 0.f, 0.f); }

__device__ __forceinline__ void fma4(float4& a, const float4& k, const float4& v) {
    a.x = fmaf(k.x, v.x, a.x);
    a.y = fmaf(k.y, v.y, a.y);
    a.z = fmaf(k.z, v.z, a.z);
    a.w = fmaf(k.w, v.w, a.w);
}

__device__ __forceinline__ void add4(float4& a, const float4& v) {
    a.x += v.x; a.y += v.y; a.z += v.z; a.w += v.w;
}

__global__ __launch_bounds__(256, 4)
void contour_integration_kernel(const float* __restrict__ x,
                                const float* __restrict__ ker,
                                float* __restrict__ out) {
    const int c4 = threadIdx.x;                       // 0..63
    const int w  = blockIdx.x * W_TILE + threadIdx.y; // 0..55
    const int h0 = blockIdx.y * H_SEG;
    const int b  = blockIdx.z;

    const bool wl = (w > 0);
    const bool wr = (w < WD - 1);
    const float4 z = f4z();

    // Per-channel taps; left/right column taps zeroed at w-boundary so the
    // (clamped) halo loads contribute nothing. Center (1,1) excluded.
    const float4* kp = (const float4*)ker;
    const float4 k00 = wl ? kp[0 * C4D + c4] : z;
    const float4 k01 =      kp[1 * C4D + c4];
    const float4 k02 = wr ? kp[2 * C4D + c4] : z;
    const float4 k10 = wl ? kp[3 * C4D + c4] : z;
    const float4 k12 = wr ? kp[5 * C4D + c4] : z;
    const float4 k20 = wl ? kp[6 * C4D + c4] : z;
    const float4 k21 =      kp[7 * C4D + c4];
    const float4 k22 = wr ? kp[8 * C4D + c4] : z;

    // Clamped halo offsets: at the boundary, load the center again (L1 hit).
    const int offL = wl ? -C4D : 0;
    const int offR = wr ?  C4D : 0;

    const float4* xp = (const float4*)x;
    float4*       op = (float4*)out;

    const long rowstride = (long)WD * C4D;
    const long base = ((long)b * HD * WD + (long)w) * C4D + c4;

    float4 a0, a1;   // a0: partial of out[row]; a1: partial of out[row+1]

    // Input row h0-1 -> top-tap contribution to out[h0].
    if (h0 > 0) {
        const float4* p = xp + base + (long)(h0 - 1) * rowstride;
        const float4 xl = p[offL], xc = p[0], xr = p[offR];
        float4 t = z;
        fma4(t, k00, xl); fma4(t, k01, xc); fma4(t, k02, xr);
        a1 = t;
    } else {
        a1 = z;
    }

    // Input row h0 -> mid taps + residual to out[h0]; top taps to out[h0+1].
    {
        const float4* p = xp + base + (long)h0 * rowstride;
        const float4 xl = p[offL], xc = p[0], xr = p[offR];
        a0 = a1;
        add4(a0, xc);                       // residual
        fma4(a0, k10, xl); fma4(a0, k12, xr);
        float4 t = z;
        fma4(t, k00, xl); fma4(t, k01, xc); fma4(t, k02, xr);
        a1 = t;
    }

    // Input rows h0+1 .. h0+H_SEG-1: finalize out[hi-1], advance partials.
    #pragma unroll
    for (int i = 1; i < H_SEG; ++i) {
        const long hi = h0 + i;
        const float4* p = xp + base + hi * rowstride;
        const float4 xl = p[offL], xc = p[0], xr = p[offR];

        float4 o = a0;                      // bottom taps close out[hi-1]
        fma4(o, k20, xl); fma4(o, k21, xc); fma4(o, k22, xr);
        __stcs(op + base + (hi - 1) * rowstride, o);

        a0 = a1;
        add4(a0, xc);
        fma4(a0, k10, xl); fma4(a0, k12, xr);
        float4 t = z;
        fma4(t, k00, xl); fma4(t, k01, xc); fma4(t, k02, xr);
        a1 = t;
    }

    // Input row h0+H_SEG -> bottom-tap contribution to out[h0+H_SEG-1].
    {
        const long hb = h0 + H_SEG;
        if (hb < HD) {
            const float4* p = xp + base + hb * rowstride;
            const float4 xl = p[offL], xc = p[0], xr = p[offR];
            fma4(a0, k20, xl); fma4(a0, k21, xc); fma4(a0, k22, xr);
        }
        __stcs(op + base + (hb - 1) * rowstride, a0);
    }
}

extern "C" void kernel_launch(void* const* d_in, const int* in_sizes, int n_in,
                              void* d_out, int out_size) {
    const float* x   = (const float*)d_in[0];   // [32,56,56,256]
    const float* ker = (const float*)d_in[1];   // [3,3,256]
    float*       out = (float*)d_out;

    dim3 block(C4D, W_TILE);                    // 64 x 4 = 256 threads
    dim3 grid(WD / W_TILE, HD / H_SEG, BD);     // 14 x 4 x 32 = 1792 blocks
    contour_integration_kernel<<<grid, block>>>(x, ker, out);
}